// round 9
// baseline (speedup 1.0000x reference)
#include <cuda_runtime.h>
#include <cuda_bf16.h>
#include <mma.h>
#include <cstdint>

using namespace nvcuda;

// Problem shapes (fixed by dataset)
#define Dm   512
#define Hh   8
#define HDc  64
#define NIc  3
#define Bc   4
#define Nn   8192
#define NIi  4096

// ---------------- scratch (device globals; no allocations) ----------------
__device__ float g_q[(size_t)Bc * Nn * Dm];      // 64 MB  softmax(Q)
__device__ float g_k[(size_t)Bc * NIi * Dm];     // 32 MB  K_i (reused across i)
__device__ float g_v[(size_t)Bc * NIi * Dm];     // 32 MB  V_i (reused across i)
__device__ float g_kv[(size_t)NIc * Bc * Hh * HDc * HDc]; // 1.5 MB
__device__ float g_ksum[(size_t)NIc * Bc * Hh * HDc];
__device__ float g_out[(size_t)Bc * Nn * Dm];    // 64 MB  pre-Wo output
__device__ int   g_mask_mode;                    // 0=int32, 1=uint8/bool, 2=float32

// ---------------- mask dtype detection ----------------
__global__ void detect_mask_kernel(const unsigned char* __restrict__ m) {
    __shared__ int s_bytes_nz;
    __shared__ int s_float_bad;
    if (threadIdx.x == 0) { s_bytes_nz = 0; s_float_bad = 0; }
    __syncthreads();
    int bytes_nz = 0;
    for (int i = threadIdx.x; i < 16384; i += blockDim.x) {
        if ((i & 3) != 0 && m[i] != 0) bytes_nz = 1;
    }
    int float_bad = 0;
    const float* mf = (const float*)m;
    for (int i = threadIdx.x; i < 4096; i += blockDim.x) {
        float v = mf[i];
        if (!(v == 0.0f || v == 1.0f)) float_bad = 1;
    }
    if (bytes_nz)  atomicOr(&s_bytes_nz, 1);
    if (float_bad) atomicOr(&s_float_bad, 1);
    __syncthreads();
    if (threadIdx.x == 0) {
        int mode;
        if (!s_bytes_nz)        mode = 0;   // packed words with zero high bytes -> int32
        else if (!s_float_bad)  mode = 2;   // all exact {0.0,1.0} floats
        else                    mode = 1;   // raw bool bytes
        g_mask_mode = mode;
    }
}

__device__ __forceinline__ float mask_keep(const void* mask, int row) {
    int mode = g_mask_mode;
    if (mode == 1) return ((const unsigned char*)mask)[row] ? 1.0f : 0.0f;
    if (mode == 2) return (((const float*)mask)[row] != 0.0f) ? 1.0f : 0.0f;
    return (((const int*)mask)[row] != 0) ? 1.0f : 0.0f;
}

// ---------------- zero kv accumulators ----------------
__global__ void zero_kv_kernel(float* __restrict__ kv, float* __restrict__ ks) {
    int i = blockIdx.x * blockDim.x + threadIdx.x;
    const int NKV = NIc * Bc * Hh * HDc * HDc;
    const int NKS = NIc * Bc * Hh * HDc;
    if (i < NKV) kv[i] = 0.0f;
    if (i < NKS) ks[i] = 0.0f;
}

// ---------------- tf32 tensor-core GEMM: C[M,512] = A[M,512] @ W[512,512]^T + bias ----
// epi: 0 = none, 1 = softmax per 64-col head group, 2 = softmax + mask row zeroing
//
// Block tile 128x128, BK=32, 8 warps as 2(m) x 4(n), each warp 64x32 via 4x2
// wmma 16x16x8 tf32 fragments. Accumulators staged to a smem C-tile, then the
// proven fp32 epilogue (bias / per-head softmax / mask) runs on smem rows with
// the same (tx,ty) thread mapping as the validated FFMA kernel.
#define BKt 32
#define LDT 36            // BK + 4 pad, multiple of 4 (wmma ld requirement)
#define LDC 132           // 128 + 4 pad, multiple of 4
// dynamic smem: max(2*128*LDT, 128*LDC) floats = 16896 floats = 67584 bytes
#define SMEM_BYTES (128 * LDC * 4)

__global__ __launch_bounds__(256, 2)
void gemm_tc_kernel(const float* __restrict__ A, const float* __restrict__ W,
                    const float* __restrict__ bias, float* __restrict__ C,
                    int M, int epi, const void* __restrict__ mask) {
    extern __shared__ float sm[];
    float* Asm = sm;                       // [128][LDT]
    float* Wsm = sm + 128 * LDT;           // [128][LDT]
    float* Csm = sm;                       // [128][LDC]  (aliases load buffers, used after final sync)

    const int tid = threadIdx.x;
    const int wid = tid >> 5;
    const int m0 = blockIdx.y * 128;
    const int n0 = blockIdx.x * 128;

    const int warp_m = (wid >> 2) * 64;    // 0 or 64
    const int warp_n = (wid & 3) * 32;     // 0,32,64,96

    wmma::fragment<wmma::accumulator, 16, 16, 8, float> acc[4][2];
#pragma unroll
    for (int i = 0; i < 4; i++)
#pragma unroll
        for (int j = 0; j < 2; j++) wmma::fill_fragment(acc[i][j], 0.0f);

    // gmem -> smem loads: 128 rows x 32 floats = 1024 float4; thread = (row, 16-float half)
    const int lrow = tid >> 1;             // 0..127
    const int lco  = (tid & 1) * 16;       // 0 or 16
    const float* Aload = A + (size_t)(m0 + lrow) * Dm + lco;
    const float* Wload = W + (size_t)(n0 + lrow) * Dm + lco;

    for (int t = 0; t < Dm / BKt; t++) {   // 16 iterations
#pragma unroll
        for (int j = 0; j < 4; j++) {
            float4 va = *(const float4*)(Aload + t * BKt + j * 4);
            float4 vw = *(const float4*)(Wload + t * BKt + j * 4);
            *(float4*)&Asm[lrow * LDT + lco + j * 4] = va;
            *(float4*)&Wsm[lrow * LDT + lco + j * 4] = vw;
        }
        __syncthreads();

#pragma unroll
        for (int kk = 0; kk < BKt; kk += 8) {
            wmma::fragment<wmma::matrix_a, 16, 16, 8, wmma::precision::tf32, wmma::row_major> af[4];
            wmma::fragment<wmma::matrix_b, 16, 16, 8, wmma::precision::tf32, wmma::col_major> bf[2];
#pragma unroll
            for (int i = 0; i < 4; i++) {
                wmma::load_matrix_sync(af[i], &Asm[(warp_m + i * 16) * LDT + kk], LDT);
#pragma unroll
                for (int e = 0; e < af[i].num_elements; e++)
                    af[i].x[e] = wmma::__float_to_tf32(af[i].x[e]);
            }
#pragma unroll
            for (int j = 0; j < 2; j++) {
                // Wsm[n][k] read as col_major: element (k, n) at ptr[n*LDT + k]
                // = W[n0+warp_n+j*16+n][t*BK+kk+k]  -> exactly B = W^T.
                wmma::load_matrix_sync(bf[j], &Wsm[(warp_n + j * 16) * LDT + kk], LDT);
#pragma unroll
                for (int e = 0; e < bf[j].num_elements; e++)
                    bf[j].x[e] = wmma::__float_to_tf32(bf[j].x[e]);
            }
#pragma unroll
            for (int i = 0; i < 4; i++)
#pragma unroll
                for (int j = 0; j < 2; j++)
                    wmma::mma_sync(acc[i][j], af[i], bf[j], acc[i][j]);
        }
        __syncthreads();   // after final iter: all smem reads done -> safe to alias Csm
    }

    // stage accumulators to smem C tile
#pragma unroll
    for (int i = 0; i < 4; i++)
#pragma unroll
        for (int j = 0; j < 2; j++)
            wmma::store_matrix_sync(&Csm[(size_t)(warp_m + i * 16) * LDC + warp_n + j * 16],
                                    acc[i][j], LDC, wmma::mem_row_major);
    __syncthreads();

    // ---- epilogue: identical math/mapping to the validated fp32 kernel ----
    const int tx = tid & 15;
    const int ty = tid >> 4;

    float bv[8];
#pragma unroll
    for (int j = 0; j < 8; j++) bv[j] = bias[n0 + tx * 8 + j];

#pragma unroll
    for (int i = 0; i < 8; i++) {
        const int row = ty * 8 + i;
        float v[8];
        *(float4*)&v[0] = *(const float4*)&Csm[(size_t)row * LDC + tx * 8];
        *(float4*)&v[4] = *(const float4*)&Csm[(size_t)row * LDC + tx * 8 + 4];
#pragma unroll
        for (int j = 0; j < 8; j++) v[j] += bv[j];

        if (epi != 0) {
            // softmax over each 64-col head group; peers = lanes xor {1,2,4}
            // (same ty, same tx>>3), exactly as in the proven FFMA epilogue.
            float mx = v[0];
#pragma unroll
            for (int j = 1; j < 8; j++) mx = fmaxf(mx, v[j]);
#pragma unroll
            for (int o = 1; o < 8; o <<= 1)
                mx = fmaxf(mx, __shfl_xor_sync(0xFFFFFFFFu, mx, o));
            float e[8];
            float s = 0.0f;
#pragma unroll
            for (int j = 0; j < 8; j++) { e[j] = __expf(v[j] - mx); s += e[j]; }
#pragma unroll
            for (int o = 1; o < 8; o <<= 1)
                s += __shfl_xor_sync(0xFFFFFFFFu, s, o);
            float inv = 1.0f / s;
            float keep = 1.0f;
            if (epi == 2) keep = mask_keep(mask, m0 + row);
            inv *= keep;
#pragma unroll
            for (int j = 0; j < 8; j++) v[j] = e[j] * inv;
        }

        float* cp = C + (size_t)(m0 + row) * Dm + n0 + tx * 8;
        *(float4*)(cp + 0) = make_float4(v[0], v[1], v[2], v[3]);
        *(float4*)(cp + 4) = make_float4(v[4], v[5], v[6], v[7]);
    }
}

// ---------------- kv = k^T v, ksum = sum_s k  (one i per launch) ----------------
#define KV_SPLIT 8
__global__ __launch_bounds__(256)
void kv_kernel(const float* __restrict__ K, const float* __restrict__ V,
               float* __restrict__ kv, float* __restrict__ ksum) {
    const int split = blockIdx.x;     // 0..7
    const int h = blockIdx.y;
    const int b = blockIdx.z;
    const int s0 = split * (NIi / KV_SPLIT);  // 512 rows
    __shared__ __align__(16) float ks[8][68];
    __shared__ __align__(16) float vs[8][68];

    const int tid = threadIdx.x;
    const int tx = tid & 15;
    const int ty = tid >> 4;

    float acc[4][4];
#pragma unroll
    for (int i = 0; i < 4; i++)
#pragma unroll
        for (int j = 0; j < 4; j++) acc[i][j] = 0.0f;
    float ksum_loc = 0.0f;

    const float* Kbase = K + ((size_t)(b * NIi + s0)) * Dm + h * HDc;
    const float* Vbase = V + ((size_t)(b * NIi + s0)) * Dm + h * HDc;

    const int r  = (tid & 127) >> 4;  // 0..7
    const int c4 = (tid & 15) * 4;

    for (int s = 0; s < NIi / KV_SPLIT; s += 8) {
        if (tid < 128) {
            float4 kk = *(const float4*)(Kbase + (size_t)(s + r) * Dm + c4);
            *(float4*)&ks[r][c4] = kk;
        } else {
            float4 vv = *(const float4*)(Vbase + (size_t)(s + r) * Dm + c4);
            *(float4*)&vs[r][c4] = vv;
        }
        __syncthreads();
#pragma unroll
        for (int ss = 0; ss < 8; ss++) {
            float a[4], w[4];
            *(float4*)a = *(const float4*)&ks[ss][ty * 4];
            *(float4*)w = *(const float4*)&vs[ss][tx * 4];
#pragma unroll
            for (int i = 0; i < 4; i++)
#pragma unroll
                for (int j = 0; j < 4; j++) acc[i][j] += a[i] * w[j];
        }
        if (tid < 64) {
#pragma unroll
            for (int ss = 0; ss < 8; ss++) ksum_loc += ks[ss][tid];
        }
        __syncthreads();
    }

    float* kvb = kv + ((size_t)(b * Hh + h)) * HDc * HDc;
#pragma unroll
    for (int i = 0; i < 4; i++)
#pragma unroll
        for (int j = 0; j < 4; j++)
            atomicAdd(&kvb[(ty * 4 + i) * HDc + tx * 4 + j], acc[i][j]);
    if (tid < 64) atomicAdd(&ksum[(size_t)(b * Hh + h) * HDc + tid], ksum_loc);
}

// ---------------- out = (q + sum_i (q@kv_i)*d_inv_i) / 3 ----------------
__global__ __launch_bounds__(256)
void out_kernel(const float* __restrict__ q, const float* __restrict__ kv_all,
                const float* __restrict__ ksum_all, float* __restrict__ outb) {
    const int nt = blockIdx.x;        // 64-row tile index
    const int h = blockIdx.y;
    const int b = blockIdx.z;
    __shared__ __align__(16) float qT[64][68];   // [d][row]
    __shared__ __align__(16) float kvs[64][68];  // [d][e]
    __shared__ float ksum_s[64];
    __shared__ float dinv_s[64];

    const int tid = threadIdx.x;
    const int tx = tid & 15;
    const int ty = tid >> 4;
    const int n0 = nt * 64;

    const float* qbase = q + ((size_t)b * Nn + n0) * Dm + h * HDc;
    {
        // 64 rows x 64 d = 1024 float4s; 256 threads x 4 float4s each.
        const int r = tid >> 2;        // 0..63 (row)
        const int c4 = (tid & 3) * 4;  // d offset base
#pragma unroll
        for (int rep = 0; rep < 4; rep++) {
            const int d0 = c4 + rep * 16;
            float4 v = *(const float4*)(qbase + (size_t)r * Dm + d0);
            qT[d0 + 0][r] = v.x; qT[d0 + 1][r] = v.y;
            qT[d0 + 2][r] = v.z; qT[d0 + 3][r] = v.w;
        }
    }
    __syncthreads();

    float y[4][4];
#pragma unroll
    for (int i = 0; i < 4; i++)
#pragma unroll
        for (int j = 0; j < 4; j++)
            y[i][j] = qT[tx * 4 + j][ty * 4 + i] * (1.0f / 3.0f);

    for (int it = 0; it < NIc; it++) {
        const float* kvb = kv_all + (((size_t)it * Bc + b) * Hh + h) * HDc * HDc;
        const float* ksb = ksum_all + (((size_t)it * Bc + b) * Hh + h) * HDc;
        __syncthreads();  // previous iteration's reads of kvs done
        {
            const int d = tid >> 2;
            const int e4 = (tid & 3) * 4;
#pragma unroll
            for (int rep = 0; rep < 4; rep++)
                *(float4*)&kvs[d][e4 + rep * 16] =
                    *(const float4*)(kvb + (size_t)d * HDc + e4 + rep * 16);
        }
        if (tid < 64) ksum_s[tid] = ksb[tid];
        __syncthreads();
        if (tid < 64) {
            float dq = 0.0f;
#pragma unroll
            for (int d = 0; d < 64; d++) dq += qT[d][tid] * ksum_s[d];
            dinv_s[tid] = 1.0f / (3.0f * dq);
        }
        __syncthreads();
        float acc[4][4];
#pragma unroll
        for (int i = 0; i < 4; i++)
#pragma unroll
            for (int j = 0; j < 4; j++) acc[i][j] = 0.0f;
        for (int d = 0; d < 64; d++) {
            float a[4], w[4];
            *(float4*)a = *(const float4*)&qT[d][ty * 4];
            *(float4*)w = *(const float4*)&kvs[d][tx * 4];
#pragma unroll
            for (int i = 0; i < 4; i++)
#pragma unroll
                for (int j = 0; j < 4; j++) acc[i][j] += a[i] * w[j];
        }
#pragma unroll
        for (int i = 0; i < 4; i++) {
            float di = dinv_s[ty * 4 + i];
#pragma unroll
            for (int j = 0; j < 4; j++) y[i][j] += acc[i][j] * di;
        }
    }

    float* ob = outb + ((size_t)b * Nn + n0) * Dm + h * HDc;
#pragma unroll
    for (int i = 0; i < 4; i++) {
        float4 v = make_float4(y[i][0], y[i][1], y[i][2], y[i][3]);
        *(float4*)(ob + (size_t)(ty * 4 + i) * Dm + tx * 4) = v;
    }
}

// ---------------- host launcher ----------------
extern "C" void kernel_launch(void* const* d_in, const int* in_sizes, int n_in,
                              void* d_out, int out_size) {
    const float* x    = (const float*)d_in[0];
    const float* emb[3] = {(const float*)d_in[1], (const float*)d_in[2], (const float*)d_in[3]};
    const float* Wq   = (const float*)d_in[4];
    const float* bq   = (const float*)d_in[5];
    const float* Wk   = (const float*)d_in[6];
    const float* bk   = (const float*)d_in[7];
    const float* Wv   = (const float*)d_in[8];
    const float* bv   = (const float*)d_in[9];
    const float* Wo   = (const float*)d_in[10];
    const float* bo   = (const float*)d_in[11];
    const void*  mask[3] = {d_in[12], d_in[13], d_in[14]};
    float* out = (float*)d_out;

    float *qb, *kb, *vb, *kvb, *ksb, *ob;
    cudaGetSymbolAddress((void**)&qb, g_q);
    cudaGetSymbolAddress((void**)&kb, g_k);
    cudaGetSymbolAddress((void**)&vb, g_v);
    cudaGetSymbolAddress((void**)&kvb, g_kv);
    cudaGetSymbolAddress((void**)&ksb, g_ksum);
    cudaGetSymbolAddress((void**)&ob, g_out);

    // opt-in to 66KB dynamic smem for the tensor-core GEMM (idempotent)
    cudaFuncSetAttribute(gemm_tc_kernel,
                         cudaFuncAttributeMaxDynamicSharedMemorySize, SMEM_BYTES);

    detect_mask_kernel<<<1, 256>>>((const unsigned char*)d_in[12]);
    zero_kv_kernel<<<(NIc * Bc * Hh * HDc * HDc + 255) / 256, 256>>>(kvb, ksb);

    // Q = softmax(x @ Wq^T + bq) per head
    gemm_tc_kernel<<<dim3(Dm / 128, (Bc * Nn) / 128), 256, SMEM_BYTES>>>(
        x, Wq, bq, qb, Bc * Nn, 1, nullptr);

    for (int i = 0; i < NIc; i++) {
        // K_i = mask * softmax(emb_i @ Wk[i]^T + bk[i])
        gemm_tc_kernel<<<dim3(Dm / 128, (Bc * NIi) / 128), 256, SMEM_BYTES>>>(
            emb[i], Wk + (size_t)i * Dm * Dm, bk + (size_t)i * Dm, kb,
            Bc * NIi, 2, mask[i]);
        // V_i = emb_i @ Wv[i]^T + bv[i]
        gemm_tc_kernel<<<dim3(Dm / 128, (Bc * NIi) / 128), 256, SMEM_BYTES>>>(
            emb[i], Wv + (size_t)i * Dm * Dm, bv + (size_t)i * Dm, vb,
            Bc * NIi, 0, nullptr);
        // kv_i, ksum_i
        kv_kernel<<<dim3(KV_SPLIT, Hh, Bc), 256>>>(
            kb, vb, kvb + (size_t)i * Bc * Hh * HDc * HDc,
            ksb + (size_t)i * Bc * Hh * HDc);
    }

    // out = (q + sum_i (q @ kv_i) * d_inv_i) / 3
    out_kernel<<<dim3(Nn / 64, Hh, Bc), 256>>>(qb, kvb, ksb, ob);

    // final = out @ Wo^T + bo
    gemm_tc_kernel<<<dim3(Dm / 128, (Bc * Nn) / 128), 256, SMEM_BYTES>>>(
        ob, Wo, bo, out, Bc * Nn, 0, nullptr);
}

// round 15
// speedup vs baseline: 1.0023x; 1.0023x over previous
#include <cuda_runtime.h>
#include <cuda_bf16.h>
#include <cuda_pipeline.h>
#include <mma.h>
#include <cstdint>

using namespace nvcuda;

// Problem shapes (fixed by dataset)
#define Dm   512
#define Hh   8
#define HDc  64
#define NIc  3
#define Bc   4
#define Nn   8192
#define NIi  4096

// ---------------- scratch (device globals; no allocations) ----------------
__device__ float g_q[(size_t)Bc * Nn * Dm];      // 64 MB  softmax(Q)
__device__ float g_k[(size_t)Bc * NIi * Dm];     // 32 MB  K_i (reused across i)
__device__ float g_v[(size_t)Bc * NIi * Dm];     // 32 MB  V_i (reused across i)
__device__ float g_kv[(size_t)NIc * Bc * Hh * HDc * HDc]; // 1.5 MB
__device__ float g_ksum[(size_t)NIc * Bc * Hh * HDc];
__device__ float g_out[(size_t)Bc * Nn * Dm];    // 64 MB  pre-Wo output
__device__ int   g_mask_mode;                    // 0=int32, 1=uint8/bool, 2=float32

// ---------------- mask dtype detection ----------------
__global__ void detect_mask_kernel(const unsigned char* __restrict__ m) {
    __shared__ int s_bytes_nz;
    __shared__ int s_float_bad;
    if (threadIdx.x == 0) { s_bytes_nz = 0; s_float_bad = 0; }
    __syncthreads();
    int bytes_nz = 0;
    for (int i = threadIdx.x; i < 16384; i += blockDim.x) {
        if ((i & 3) != 0 && m[i] != 0) bytes_nz = 1;
    }
    int float_bad = 0;
    const float* mf = (const float*)m;
    for (int i = threadIdx.x; i < 4096; i += blockDim.x) {
        float v = mf[i];
        if (!(v == 0.0f || v == 1.0f)) float_bad = 1;
    }
    if (bytes_nz)  atomicOr(&s_bytes_nz, 1);
    if (float_bad) atomicOr(&s_float_bad, 1);
    __syncthreads();
    if (threadIdx.x == 0) {
        int mode;
        if (!s_bytes_nz)        mode = 0;   // packed words with zero high bytes -> int32
        else if (!s_float_bad)  mode = 2;   // all exact {0.0,1.0} floats
        else                    mode = 1;   // raw bool bytes
        g_mask_mode = mode;
    }
}

__device__ __forceinline__ float mask_keep(const void* mask, int row) {
    int mode = g_mask_mode;
    if (mode == 1) return ((const unsigned char*)mask)[row] ? 1.0f : 0.0f;
    if (mode == 2) return (((const float*)mask)[row] != 0.0f) ? 1.0f : 0.0f;
    return (((const int*)mask)[row] != 0) ? 1.0f : 0.0f;
}

// ---------------- zero kv accumulators ----------------
__global__ void zero_kv_kernel(float* __restrict__ kv, float* __restrict__ ks) {
    int i = blockIdx.x * blockDim.x + threadIdx.x;
    const int NKV = NIc * Bc * Hh * HDc * HDc;
    const int NKS = NIc * Bc * Hh * HDc;
    if (i < NKV) kv[i] = 0.0f;
    if (i < NKS) ks[i] = 0.0f;
}

// ---------------- tf32 tensor-core GEMM: C[M,512] = A[M,512] @ W[512,512]^T + bias ----
// epi: 0 = none, 1 = softmax per 64-col head group, 2 = softmax + mask row zeroing
//
// Block tile 128x128, BK=32, 8 warps as 2(m) x 4(n), each warp 64x32 via 4x2
// wmma 16x16x8 tf32 fragments. Mainloop is a 2-stage cp.async pipeline:
// tile t+1 streams gmem->smem (LDGSTS, no register staging) while tile t is
// consumed by the MMAs. Accumulators staged to a smem C-tile, then the proven
// fp32 epilogue (bias / per-head softmax / mask) runs with the same (tx,ty)
// mapping as the validated kernel.
#define BKt 32
#define LDT 36                         // BK + 4 pad, multiple of 4 (wmma ld requirement)
#define LDC 132                        // 128 + 4 pad, multiple of 4
#define STAGE_F (2 * 128 * LDT)        // floats per stage (A tile + W tile)
// dynamic smem: 2 stages = 73728 B; epilogue C tile needs 67584 B (fits, aliased)
#define SMEM_BYTES (2 * STAGE_F * 4)

__global__ __launch_bounds__(256, 2)
void gemm_tc_kernel(const float* __restrict__ A, const float* __restrict__ W,
                    const float* __restrict__ bias, float* __restrict__ C,
                    int M, int epi, const void* __restrict__ mask) {
    extern __shared__ float sm[];
    float* Csm = sm;                   // [128][LDC], aliases the stages after final sync

    const int tid = threadIdx.x;
    const int wid = tid >> 5;
    const int m0 = blockIdx.y * 128;
    const int n0 = blockIdx.x * 128;

    const int warp_m = (wid >> 2) * 64;    // 0 or 64
    const int warp_n = (wid & 3) * 32;     // 0,32,64,96

    wmma::fragment<wmma::accumulator, 16, 16, 8, float> acc[4][2];
#pragma unroll
    for (int i = 0; i < 4; i++)
#pragma unroll
        for (int j = 0; j < 2; j++) wmma::fill_fragment(acc[i][j], 0.0f);

    // gmem -> smem copy geometry: 128 rows x 32 floats per matrix;
    // thread = (row, 16-float half), 4 x 16B cp.async per matrix per tile.
    const int lrow = tid >> 1;             // 0..127
    const int lco  = (tid & 1) * 16;       // 0 or 16
    const float* Aload = A + (size_t)(m0 + lrow) * Dm + lco;
    const float* Wload = W + (size_t)(n0 + lrow) * Dm + lco;
    const int KT = Dm / BKt;               // 16

    // issue async copies for K-tile t into stage s
    auto issue_tile = [&](int t, int s) {
        float* dA = sm + s * STAGE_F + lrow * LDT + lco;
        float* dW = sm + s * STAGE_F + 128 * LDT + lrow * LDT + lco;
        const float* sA = Aload + t * BKt;
        const float* sW = Wload + t * BKt;
#pragma unroll
        for (int j = 0; j < 4; j++) {
            __pipeline_memcpy_async(dA + j * 4, sA + j * 4, 16);
            __pipeline_memcpy_async(dW + j * 4, sW + j * 4, 16);
        }
        __pipeline_commit();
    };

    issue_tile(0, 0);                      // prologue

    for (int t = 0; t < KT; t++) {
        const int cur = t & 1;
        if (t + 1 < KT) issue_tile(t + 1, cur ^ 1);
        __pipeline_wait_prior((t + 1 < KT) ? 1 : 0);   // tile t landed (per-thread)
        __syncthreads();                                // all threads' copies visible

        const float* Asm = sm + cur * STAGE_F;
        const float* Wsm = Asm + 128 * LDT;

#pragma unroll
        for (int kk = 0; kk < BKt; kk += 8) {
            wmma::fragment<wmma::matrix_a, 16, 16, 8, wmma::precision::tf32, wmma::row_major> af[4];
            wmma::fragment<wmma::matrix_b, 16, 16, 8, wmma::precision::tf32, wmma::col_major> bf[2];
#pragma unroll
            for (int i = 0; i < 4; i++) {
                wmma::load_matrix_sync(af[i], &Asm[(warp_m + i * 16) * LDT + kk], LDT);
#pragma unroll
                for (int e = 0; e < af[i].num_elements; e++)
                    af[i].x[e] = wmma::__float_to_tf32(af[i].x[e]);
            }
#pragma unroll
            for (int j = 0; j < 2; j++) {
                // Wsm[n][k] read as col_major: element (k, n) at ptr[n*LDT + k]
                // = W[n0+warp_n+j*16+n][t*BK+kk+k]  -> exactly B = W^T.
                wmma::load_matrix_sync(bf[j], &Wsm[(warp_n + j * 16) * LDT + kk], LDT);
#pragma unroll
                for (int e = 0; e < bf[j].num_elements; e++)
                    bf[j].x[e] = wmma::__float_to_tf32(bf[j].x[e]);
            }
#pragma unroll
            for (int i = 0; i < 4; i++)
#pragma unroll
                for (int j = 0; j < 2; j++)
                    wmma::mma_sync(acc[i][j], af[i], bf[j], acc[i][j]);
        }
        __syncthreads();   // stage consumed; next iteration may overwrite it
    }

    // stage accumulators to smem C tile (aliases the pipeline stages; safe after sync)
#pragma unroll
    for (int i = 0; i < 4; i++)
#pragma unroll
        for (int j = 0; j < 2; j++)
            wmma::store_matrix_sync(&Csm[(size_t)(warp_m + i * 16) * LDC + warp_n + j * 16],
                                    acc[i][j], LDC, wmma::mem_row_major);
    __syncthreads();

    // ---- epilogue: identical math/mapping to the validated kernel ----
    const int tx = tid & 15;
    const int ty = tid >> 4;

    float bv[8];
#pragma unroll
    for (int j = 0; j < 8; j++) bv[j] = bias[n0 + tx * 8 + j];

#pragma unroll
    for (int i = 0; i < 8; i++) {
        const int row = ty * 8 + i;
        float v[8];
        *(float4*)&v[0] = *(const float4*)&Csm[(size_t)row * LDC + tx * 8];
        *(float4*)&v[4] = *(const float4*)&Csm[(size_t)row * LDC + tx * 8 + 4];
#pragma unroll
        for (int j = 0; j < 8; j++) v[j] += bv[j];

        if (epi != 0) {
            // softmax over each 64-col head group; peers = lanes xor {1,2,4}
            // (same ty, same tx>>3), exactly as in the proven epilogue.
            float mx = v[0];
#pragma unroll
            for (int j = 1; j < 8; j++) mx = fmaxf(mx, v[j]);
#pragma unroll
            for (int o = 1; o < 8; o <<= 1)
                mx = fmaxf(mx, __shfl_xor_sync(0xFFFFFFFFu, mx, o));
            float e[8];
            float s = 0.0f;
#pragma unroll
            for (int j = 0; j < 8; j++) { e[j] = __expf(v[j] - mx); s += e[j]; }
#pragma unroll
            for (int o = 1; o < 8; o <<= 1)
                s += __shfl_xor_sync(0xFFFFFFFFu, s, o);
            float inv = 1.0f / s;
            float keep = 1.0f;
            if (epi == 2) keep = mask_keep(mask, m0 + row);
            inv *= keep;
#pragma unroll
            for (int j = 0; j < 8; j++) v[j] = e[j] * inv;
        }

        float* cp = C + (size_t)(m0 + row) * Dm + n0 + tx * 8;
        *(float4*)(cp + 0) = make_float4(v[0], v[1], v[2], v[3]);
        *(float4*)(cp + 4) = make_float4(v[4], v[5], v[6], v[7]);
    }
}

// ---------------- kv = k^T v, ksum = sum_s k  (one i per launch) ----------------
#define KV_SPLIT 8
__global__ __launch_bounds__(256)
void kv_kernel(const float* __restrict__ K, const float* __restrict__ V,
               float* __restrict__ kv, float* __restrict__ ksum) {
    const int split = blockIdx.x;     // 0..7
    const int h = blockIdx.y;
    const int b = blockIdx.z;
    const int s0 = split * (NIi / KV_SPLIT);  // 512 rows
    __shared__ __align__(16) float ks[8][68];
    __shared__ __align__(16) float vs[8][68];

    const int tid = threadIdx.x;
    const int tx = tid & 15;
    const int ty = tid >> 4;

    float acc[4][4];
#pragma unroll
    for (int i = 0; i < 4; i++)
#pragma unroll
        for (int j = 0; j < 4; j++) acc[i][j] = 0.0f;
    float ksum_loc = 0.0f;

    const float* Kbase = K + ((size_t)(b * NIi + s0)) * Dm + h * HDc;
    const float* Vbase = V + ((size_t)(b * NIi + s0)) * Dm + h * HDc;

    const int r  = (tid & 127) >> 4;  // 0..7
    const int c4 = (tid & 15) * 4;

    for (int s = 0; s < NIi / KV_SPLIT; s += 8) {
        if (tid < 128) {
            float4 kk = *(const float4*)(Kbase + (size_t)(s + r) * Dm + c4);
            *(float4*)&ks[r][c4] = kk;
        } else {
            float4 vv = *(const float4*)(Vbase + (size_t)(s + r) * Dm + c4);
            *(float4*)&vs[r][c4] = vv;
        }
        __syncthreads();
#pragma unroll
        for (int ss = 0; ss < 8; ss++) {
            float a[4], w[4];
            *(float4*)a = *(const float4*)&ks[ss][ty * 4];
            *(float4*)w = *(const float4*)&vs[ss][tx * 4];
#pragma unroll
            for (int i = 0; i < 4; i++)
#pragma unroll
                for (int j = 0; j < 4; j++) acc[i][j] += a[i] * w[j];
        }
        if (tid < 64) {
#pragma unroll
            for (int ss = 0; ss < 8; ss++) ksum_loc += ks[ss][tid];
        }
        __syncthreads();
    }

    float* kvb = kv + ((size_t)(b * Hh + h)) * HDc * HDc;
#pragma unroll
    for (int i = 0; i < 4; i++)
#pragma unroll
        for (int j = 0; j < 4; j++)
            atomicAdd(&kvb[(ty * 4 + i) * HDc + tx * 4 + j], acc[i][j]);
    if (tid < 64) atomicAdd(&ksum[(size_t)(b * Hh + h) * HDc + tid], ksum_loc);
}

// ---------------- out = (q + sum_i (q@kv_i)*d_inv_i) / 3 ----------------
__global__ __launch_bounds__(256)
void out_kernel(const float* __restrict__ q, const float* __restrict__ kv_all,
                const float* __restrict__ ksum_all, float* __restrict__ outb) {
    const int nt = blockIdx.x;        // 64-row tile index
    const int h = blockIdx.y;
    const int b = blockIdx.z;
    __shared__ __align__(16) float qT[64][68];   // [d][row]
    __shared__ __align__(16) float kvs[64][68];  // [d][e]
    __shared__ float ksum_s[64];
    __shared__ float dinv_s[64];

    const int tid = threadIdx.x;
    const int tx = tid & 15;
    const int ty = tid >> 4;
    const int n0 = nt * 64;

    const float* qbase = q + ((size_t)b * Nn + n0) * Dm + h * HDc;
    {
        // 64 rows x 64 d = 1024 float4s; 256 threads x 4 float4s each.
        const int r = tid >> 2;        // 0..63 (row)
        const int c4 = (tid & 3) * 4;  // d offset base
#pragma unroll
        for (int rep = 0; rep < 4; rep++) {
            const int d0 = c4 + rep * 16;
            float4 v = *(const float4*)(qbase + (size_t)r * Dm + d0);
            qT[d0 + 0][r] = v.x; qT[d0 + 1][r] = v.y;
            qT[d0 + 2][r] = v.z; qT[d0 + 3][r] = v.w;
        }
    }
    __syncthreads();

    float y[4][4];
#pragma unroll
    for (int i = 0; i < 4; i++)
#pragma unroll
        for (int j = 0; j < 4; j++)
            y[i][j] = qT[tx * 4 + j][ty * 4 + i] * (1.0f / 3.0f);

    for (int it = 0; it < NIc; it++) {
        const float* kvb = kv_all + (((size_t)it * Bc + b) * Hh + h) * HDc * HDc;
        const float* ksb = ksum_all + (((size_t)it * Bc + b) * Hh + h) * HDc;
        __syncthreads();  // previous iteration's reads of kvs done
        {
            const int d = tid >> 2;
            const int e4 = (tid & 3) * 4;
#pragma unroll
            for (int rep = 0; rep < 4; rep++)
                *(float4*)&kvs[d][e4 + rep * 16] =
                    *(const float4*)(kvb + (size_t)d * HDc + e4 + rep * 16);
        }
        if (tid < 64) ksum_s[tid] = ksb[tid];
        __syncthreads();
        if (tid < 64) {
            float dq = 0.0f;
#pragma unroll
            for (int d = 0; d < 64; d++) dq += qT[d][tid] * ksum_s[d];
            dinv_s[tid] = 1.0f / (3.0f * dq);
        }
        __syncthreads();
        float acc[4][4];
#pragma unroll
        for (int i = 0; i < 4; i++)
#pragma unroll
            for (int j = 0; j < 4; j++) acc[i][j] = 0.0f;
        for (int d = 0; d < 64; d++) {
            float a[4], w[4];
            *(float4*)a = *(const float4*)&qT[d][ty * 4];
            *(float4*)w = *(const float4*)&kvs[d][tx * 4];
#pragma unroll
            for (int i = 0; i < 4; i++)
#pragma unroll
                for (int j = 0; j < 4; j++) acc[i][j] += a[i] * w[j];
        }
#pragma unroll
        for (int i = 0; i < 4; i++) {
            float di = dinv_s[ty * 4 + i];
#pragma unroll
            for (int j = 0; j < 4; j++) y[i][j] += acc[i][j] * di;
        }
    }

    float* ob = outb + ((size_t)b * Nn + n0) * Dm + h * HDc;
#pragma unroll
    for (int i = 0; i < 4; i++) {
        float4 v = make_float4(y[i][0], y[i][1], y[i][2], y[i][3]);
        *(float4*)(ob + (size_t)(ty * 4 + i) * Dm + tx * 4) = v;
    }
}

// ---------------- host launcher ----------------
extern "C" void kernel_launch(void* const* d_in, const int* in_sizes, int n_in,
                              void* d_out, int out_size) {
    const float* x    = (const float*)d_in[0];
    const float* emb[3] = {(const float*)d_in[1], (const float*)d_in[2], (const float*)d_in[3]};
    const float* Wq   = (const float*)d_in[4];
    const float* bq   = (const float*)d_in[5];
    const float* Wk   = (const float*)d_in[6];
    const float* bk   = (const float*)d_in[7];
    const float* Wv   = (const float*)d_in[8];
    const float* bv   = (const float*)d_in[9];
    const float* Wo   = (const float*)d_in[10];
    const float* bo   = (const float*)d_in[11];
    const void*  mask[3] = {d_in[12], d_in[13], d_in[14]};
    float* out = (float*)d_out;

    float *qb, *kb, *vb, *kvb, *ksb, *ob;
    cudaGetSymbolAddress((void**)&qb, g_q);
    cudaGetSymbolAddress((void**)&kb, g_k);
    cudaGetSymbolAddress((void**)&vb, g_v);
    cudaGetSymbolAddress((void**)&kvb, g_kv);
    cudaGetSymbolAddress((void**)&ksb, g_ksum);
    cudaGetSymbolAddress((void**)&ob, g_out);

    // opt-in to 72KB dynamic smem for the tensor-core GEMM (idempotent)
    cudaFuncSetAttribute(gemm_tc_kernel,
                         cudaFuncAttributeMaxDynamicSharedMemorySize, SMEM_BYTES);

    detect_mask_kernel<<<1, 256>>>((const unsigned char*)d_in[12]);
    zero_kv_kernel<<<(NIc * Bc * Hh * HDc * HDc + 255) / 256, 256>>>(kvb, ksb);

    // Q = softmax(x @ Wq^T + bq) per head
    gemm_tc_kernel<<<dim3(Dm / 128, (Bc * Nn) / 128), 256, SMEM_BYTES>>>(
        x, Wq, bq, qb, Bc * Nn, 1, nullptr);

    for (int i = 0; i < NIc; i++) {
        // K_i = mask * softmax(emb_i @ Wk[i]^T + bk[i])
        gemm_tc_kernel<<<dim3(Dm / 128, (Bc * NIi) / 128), 256, SMEM_BYTES>>>(
            emb[i], Wk + (size_t)i * Dm * Dm, bk + (size_t)i * Dm, kb,
            Bc * NIi, 2, mask[i]);
        // V_i = emb_i @ Wv[i]^T + bv[i]
        gemm_tc_kernel<<<dim3(Dm / 128, (Bc * NIi) / 128), 256, SMEM_BYTES>>>(
            emb[i], Wv + (size_t)i * Dm * Dm, bv + (size_t)i * Dm, vb,
            Bc * NIi, 0, nullptr);
        // kv_i, ksum_i
        kv_kernel<<<dim3(KV_SPLIT, Hh, Bc), 256>>>(
            kb, vb, kvb + (size_t)i * Bc * Hh * HDc * HDc,
            ksb + (size_t)i * Bc * Hh * HDc);
    }

    // out = (q + sum_i (q @ kv_i) * d_inv_i) / 3
    out_kernel<<<dim3(Nn / 64, Hh, Bc), 256>>>(qb, kvb, ksb, ob);

    // final = out @ Wo^T + bo
    gemm_tc_kernel<<<dim3(Dm / 128, (Bc * Nn) / 128), 256, SMEM_BYTES>>>(
        ob, Wo, bo, out, Bc * Nn, 0, nullptr);
}